// round 11
// baseline (speedup 1.0000x reference)
#include <cuda_runtime.h>
#include <cuda_bf16.h>
#include <math_constants.h>
#include <cstdint>

// Problem constants
#define B_      4096
#define N_      4096
#define D_      512
#define GW      64
#define KCH     64            // bf16 K per chunk (128B rows)
#define NCH     (D_/KCH)      // 8 chunks
#define TM_     128
#define TN_     128
#define NCOLBLK (N_/TN_)      // 32
#define NSTAGE  3
#define STAGE_BYTES 32768     // A 16KB + B 16KB
#define SM_TOTAL (NSTAGE*STAGE_BYTES)   // 96 KB -> 2 CTAs/SM
#define BAND    0.35f         // covers bf16 coarse error + bf16 store quantization
#define MAXCAND 128
#define RW      8             // refine warps (rows) per block

// Epilogue staging: bf16 tile [128][136] (272B row stride; bank-conflict-free)
#define STG_STRIDE 136
#define SM_STAGE_OFF 8192

// Scratch globals
__device__ float g_xsq[B_];
__device__ float g_wsq[N_];
__device__ float g_pval[NCOLBLK * B_];                     // per-tile min of c
__device__ __align__(16) __nv_bfloat16 g_Ab[(size_t)B_ * D_];   // 4 MB
__device__ __align__(16) __nv_bfloat16 g_Bb[(size_t)N_ * D_];   // 4 MB
__device__ __align__(16) __nv_bfloat16 g_Dc[(size_t)B_ * N_];   // 32 MB: c = wsq - 2*dot

// ---------------------------------------------------------------------------
__device__ __forceinline__ uint32_t smem_to_u32(const void* p) {
    uint32_t a;
    asm("{ .reg .u64 t; cvta.to.shared.u64 t, %1; cvt.u32.u64 %0, t; }"
        : "=r"(a) : "l"(p));
    return a;
}

#define CP_ASYNC16(dst, src) \
    asm volatile("cp.async.cg.shared.global [%0], [%1], 16;" \
        :: "r"(dst), "l"(src) : "memory")
#define CP_COMMIT()  asm volatile("cp.async.commit_group;" ::: "memory")
#define CP_WAIT1()   asm volatile("cp.async.wait_group 1;"  ::: "memory")
#define CP_WAIT0()   asm volatile("cp.async.wait_group 0;"  ::: "memory")

#define LDSM4(r0, r1, r2, r3, addr) \
    asm volatile("ldmatrix.sync.aligned.m8n8.x4.shared.b16 {%0,%1,%2,%3}, [%4];" \
        : "=r"(r0), "=r"(r1), "=r"(r2), "=r"(r3) : "r"(addr))

#define MMA_BF16(d, a, b0v, b1v) \
    asm volatile("mma.sync.aligned.m16n8k16.row.col.f32.bf16.bf16.f32 " \
        "{%0,%1,%2,%3},{%4,%5,%6,%7},{%8,%9},{%0,%1,%2,%3};" \
        : "+f"((d)[0]), "+f"((d)[1]), "+f"((d)[2]), "+f"((d)[3]) \
        : "r"((a)[0]), "r"((a)[1]), "r"((a)[2]), "r"((a)[3]), \
          "r"(b0v), "r"(b1v))

// ---------------------------------------------------------------------------
// Kernel 1: fused row sum-of-squares + fp32->bf16 conversion.
// ---------------------------------------------------------------------------
__global__ void prep_kernel(const float* __restrict__ X,
                            const float* __restrict__ Wt) {
    int warp = (blockIdx.x * blockDim.x + threadIdx.x) >> 5;
    int lane = threadIdx.x & 31;
    if (warp >= B_ + N_) return;
    const bool isW = warp >= B_;
    const int row = isW ? warp - B_ : warp;
    const float* src = isW ? Wt : X;
    __nv_bfloat16* dst = isW ? g_Bb : g_Ab;

    const float4* p = (const float4*)(src + (size_t)row * D_);
    ushort4* d4 = (ushort4*)(dst + (size_t)row * D_);
    float s = 0.f;
    #pragma unroll
    for (int i = 0; i < 4; i++) {
        int v4 = lane + i * 32;
        float4 v = p[v4];
        s = fmaf(v.x, v.x, s); s = fmaf(v.y, v.y, s);
        s = fmaf(v.z, v.z, s); s = fmaf(v.w, v.w, s);
        ushort4 h;
        h.x = __bfloat16_as_ushort(__float2bfloat16_rn(v.x));
        h.y = __bfloat16_as_ushort(__float2bfloat16_rn(v.y));
        h.z = __bfloat16_as_ushort(__float2bfloat16_rn(v.z));
        h.w = __bfloat16_as_ushort(__float2bfloat16_rn(v.w));
        d4[v4] = h;
    }
    #pragma unroll
    for (int o = 16; o; o >>= 1) s += __shfl_xor_sync(0xffffffffu, s, o);
    if (lane == 0) { if (isW) g_wsq[row] = s; else g_xsq[row] = s; }
}

// ---------------------------------------------------------------------------
// Kernel 2: COARSE bf16 GEMM (M=128, N=128, K=512), m16n8k16.
// Mainloop identical to the verified R9 kernel; epilogue now stages the
// bf16 c-tile in smem and streams it to g_Dc fully coalesced.
// ---------------------------------------------------------------------------
__device__ __forceinline__ void load_stage(uint32_t sA, uint32_t sB,
                                           int arow0, int brow0, int kc0,
                                           int tid) {
    #pragma unroll
    for (int it = 0; it < 4; it++) {
        int id = tid + it * 256;
        int m = id >> 3, ch = id & 7;
        int chs = ch ^ (m & 7);
        CP_ASYNC16(sA + m * 128 + chs * 16,
                   g_Ab + (size_t)(arow0 + m) * D_ + kc0 + ch * 8);
    }
    #pragma unroll
    for (int it = 0; it < 4; it++) {
        int id = tid + it * 256;
        int n = id >> 3, ch = id & 7;
        int chs = ch ^ (n & 7);
        CP_ASYNC16(sB + n * 128 + chs * 16,
                   g_Bb + (size_t)(brow0 + n) * D_ + kc0 + ch * 8);
    }
}

extern "C" __global__ void __launch_bounds__(256, 2)
dist_tc_kernel() {
    extern __shared__ char smem[];
    const uint32_t sb = smem_to_u32(smem);
    const int tid = threadIdx.x;
    const int wid = tid >> 5;
    const int l   = tid & 31;
    const int rowBlk = blockIdx.y;
    const int colBlk = blockIdx.x;

    const int wm = (wid >> 2) * 64;
    const int wn = (wid & 3) * 32;
    const int arow0 = rowBlk * TM_;
    const int brow0 = colBlk * TN_;

    const int mrow = (l & 7) + ((l >> 3) & 1) * 8;
    const int aAdd = l >> 4;
    const int nrow = (l & 7) + (l >> 4) * 8;
    const int bAdd = (l >> 3) & 1;

    uint32_t aRowOff[4]; int aXr[4];
    #pragma unroll
    for (int i = 0; i < 4; i++) {
        int r = wm + i * 16 + mrow;
        aRowOff[i] = r * 128; aXr[i] = r & 7;
    }
    uint32_t bRowOff[2]; int bXr[2];
    #pragma unroll
    for (int jj = 0; jj < 2; jj++) {
        int r = wn + jj * 16 + nrow;
        bRowOff[jj] = r * 128; bXr[jj] = r & 7;
    }

    float acc[4][4][4];
    #pragma unroll
    for (int i = 0; i < 4; i++)
        #pragma unroll
        for (int j = 0; j < 4; j++)
            #pragma unroll
            for (int q = 0; q < 4; q++) acc[i][j][q] = 0.f;

    load_stage(sb, sb + 16384, arow0, brow0, 0, tid);
    CP_COMMIT();
    load_stage(sb + STAGE_BYTES, sb + STAGE_BYTES + 16384,
               arow0, brow0, KCH, tid);
    CP_COMMIT();

    for (int c = 0; c < NCH; c++) {
        CP_WAIT1();
        __syncthreads();

        if (c + 2 < NCH) {
            uint32_t st = sb + ((c + 2) % NSTAGE) * STAGE_BYTES;
            load_stage(st, st + 16384, arow0, brow0, (c + 2) * KCH, tid);
        }
        CP_COMMIT();

        const uint32_t Ab = sb + (c % NSTAGE) * STAGE_BYTES;
        const uint32_t Bb = Ab + 16384;

        #pragma unroll
        for (int ks = 0; ks < 4; ks++) {
            uint32_t ar[4][4];
            #pragma unroll
            for (int i = 0; i < 4; i++)
                LDSM4(ar[i][0], ar[i][1], ar[i][2], ar[i][3],
                      Ab + aRowOff[i] + (uint32_t)(((ks * 2 + aAdd) ^ aXr[i]) * 16));
            uint32_t br[4][2];
            #pragma unroll
            for (int jj = 0; jj < 2; jj++) {
                uint32_t r0, r1, r2, r3;
                LDSM4(r0, r1, r2, r3,
                      Bb + bRowOff[jj] + (uint32_t)(((ks * 2 + bAdd) ^ bXr[jj]) * 16));
                br[jj * 2][0] = r0;      br[jj * 2][1] = r1;
                br[jj * 2 + 1][0] = r2;  br[jj * 2 + 1][1] = r3;
            }
            #pragma unroll
            for (int i = 0; i < 4; i++)
                #pragma unroll
                for (int j = 0; j < 4; j++)
                    MMA_BF16(acc[i][j], ar[i], br[j][0], br[j][1]);
        }
    }
    CP_WAIT0();
    __syncthreads();

    // ---- epilogue: c = wsq - 2*dot -> smem stage + per-tile fp32 min ----
    float ws[4][2];
    #pragma unroll
    for (int j = 0; j < 4; j++) {
        ws[j][0] = g_wsq[brow0 + wn + j * 8 + (l & 3) * 2];
        ws[j][1] = g_wsq[brow0 + wn + j * 8 + (l & 3) * 2 + 1];
    }

    float* sVal = (float*)smem;                                   // [128][4]
    __nv_bfloat16* sStage = (__nv_bfloat16*)(smem + SM_STAGE_OFF); // [128][136]

    #pragma unroll
    for (int i = 0; i < 4; i++) {
        #pragma unroll
        for (int h = 0; h < 2; h++) {
            int lrow = wm + i * 16 + h * 8 + (l >> 2);
            float bv = CUDART_INF_F;
            #pragma unroll
            for (int j = 0; j < 4; j++) {
                float cx = ws[j][0] - 2.0f * acc[i][j][h * 2 + 0];
                float cy = ws[j][1] - 2.0f * acc[i][j][h * 2 + 1];
                bv = fminf(bv, fminf(cx, cy));
                __nv_bfloat162 hh;
                hh.x = __float2bfloat16_rn(cx);
                hh.y = __float2bfloat16_rn(cy);
                *(__nv_bfloat162*)&sStage[lrow * STG_STRIDE + wn + j * 8 + (l & 3) * 2] = hh;
            }
            #pragma unroll
            for (int o = 1; o <= 2; o <<= 1)
                bv = fminf(bv, __shfl_xor_sync(0xffffffffu, bv, o));
            if ((l & 3) == 0) sVal[lrow * 4 + (wid & 3)] = bv;
        }
    }
    __syncthreads();

    if (tid < TM_) {
        float bv = fminf(fminf(sVal[tid * 4], sVal[tid * 4 + 1]),
                         fminf(sVal[tid * 4 + 2], sVal[tid * 4 + 3]));
        g_pval[colBlk * B_ + arow0 + tid] = bv;
    }

    // coalesced tile store: 2 threads per row, 128B each
    {
        int r = tid >> 1, half = tid & 1;
        const uint4* src = (const uint4*)(sStage + r * STG_STRIDE + half * 64);
        uint4* dst = (uint4*)(g_Dc + (size_t)(arow0 + r) * N_ + brow0 + half * 64);
        #pragma unroll
        for (int i = 0; i < 8; i++) dst[i] = src[i];
    }
}

// ---------------------------------------------------------------------------
// Kernel 3: warp-per-row refine. Coarse min over partials, uint4 scan of
// the bf16 c-row, exact fp32 recompute of candidates (shfl-only).
// ---------------------------------------------------------------------------
__global__ void __launch_bounds__(256)
refine_kernel(const float* __restrict__ X, const float* __restrict__ Wt,
              float* __restrict__ out) {
    const int w    = threadIdx.x >> 5;
    const int lane = threadIdx.x & 31;
    const int row  = blockIdx.x * RW + w;

    __shared__ int s_cand[RW][MAXCAND];
    __shared__ int s_cnt[RW];

    // 1) coarse row min of c from the 32 tile partials
    float m = g_pval[lane * B_ + row];
    #pragma unroll
    for (int o = 16; o; o >>= 1)
        m = fminf(m, __shfl_xor_sync(0xffffffffu, m, o));
    const float thresh = m + BAND;
    if (lane == 0) s_cnt[w] = 0;
    __syncwarp();

    // 2) candidate scan (8 bf16 per uint4 load)
    const uint4* p4 = (const uint4*)(g_Dc + (size_t)row * N_);
    #pragma unroll 4
    for (int it = 0; it < 16; it++) {
        uint4 v = p4[lane + it * 32];
        uint32_t wv[4] = {v.x, v.y, v.z, v.w};
        int colbase = (lane + it * 32) * 8;
        #pragma unroll
        for (int k = 0; k < 4; k++) {
            __nv_bfloat162 hv = *(__nv_bfloat162*)&wv[k];
            float c0 = __bfloat162float(hv.x);
            float c1 = __bfloat162float(hv.y);
            if (c0 < thresh) {
                int p = atomicAdd(&s_cnt[w], 1);
                if (p < MAXCAND) s_cand[w][p] = colbase + k * 2;
            }
            if (c1 < thresh) {
                int p = atomicAdd(&s_cnt[w], 1);
                if (p < MAXCAND) s_cand[w][p] = colbase + k * 2 + 1;
            }
        }
    }
    __syncwarp();
    const int cnt = min(s_cnt[w], MAXCAND);

    // 3) exact fp32 evaluation of candidates
    float xr[16];
    #pragma unroll
    for (int i = 0; i < 16; i++) xr[i] = X[(size_t)row * D_ + lane + i * 32];
    const float xs = g_xsq[row];

    float bestV = CUDART_INF_F;
    int   bestI = 0x7fffffff;
    for (int c = 0; c < cnt; c++) {
        int col = s_cand[w][c];
        const float* wr = Wt + (size_t)col * D_;
        float part = 0.f;
        #pragma unroll
        for (int i = 0; i < 16; i++)
            part = fmaf(xr[i], wr[lane + i * 32], part);
        #pragma unroll
        for (int o = 16; o; o >>= 1)
            part += __shfl_xor_sync(0xffffffffu, part, o);
        float v = fmaxf((xs - 2.0f * part) + g_wsq[col], 0.0f);
        if (v < bestV || (v == bestV && col < bestI)) { bestV = v; bestI = col; }
    }

    if (lane == 0) {
        out[row * 2 + 0]  = (float)(bestI >> 6);
        out[row * 2 + 1]  = (float)(bestI & (GW - 1));
        out[2 * B_ + row] = sqrtf(bestV);
    }
}

// ---------------------------------------------------------------------------
extern "C" void kernel_launch(void* const* d_in, const int* in_sizes, int n_in,
                              void* d_out, int out_size) {
    const float* X  = (const float*)d_in[0];
    const float* Wt = (const float*)d_in[1];
    float* out = (float*)d_out;

    cudaFuncSetAttribute(dist_tc_kernel,
                         cudaFuncAttributeMaxDynamicSharedMemorySize, SM_TOTAL);

    // 1) fused sqsum + bf16 conversion
    prep_kernel<<<(B_ + N_) / 8, 256>>>(X, Wt);

    // 2) coarse bf16 distance GEMM (K=512, m16n8k16)
    dim3 grid(N_ / TN_, B_ / TM_);   // (32, 32)
    dist_tc_kernel<<<grid, 256, SM_TOTAL>>>();

    // 3) warp-per-row candidate refine + outputs
    refine_kernel<<<B_ / RW, 256>>>(X, Wt, out);
}

// round 12
// speedup vs baseline: 1.0603x; 1.0603x over previous
#include <cuda_runtime.h>
#include <cuda_bf16.h>
#include <math_constants.h>
#include <cstdint>

// Problem constants
#define B_      4096
#define N_      4096
#define D_      512
#define GW      64
#define KCH     64            // bf16 K per chunk (128B rows)
#define NCH     (D_/KCH)      // 8 chunks
#define TM_     128
#define TN_     128
#define NCOLBLK (N_/TN_)      // 32
#define NSTAGE  3
#define STAGE_BYTES 32768     // A 16KB + B 16KB
#define SM_TOTAL (NSTAGE*STAGE_BYTES)   // 96 KB -> 2 CTAs/SM
#define BAND    0.35f         // covers bf16 coarse error + bf16 store quantization
#define MAXCAND 128
#define RW      8             // refine warps (rows) per block

// Scratch globals
__device__ float g_xsq[B_];
__device__ float g_wsq[N_];
__device__ float g_pval[NCOLBLK * B_];                     // per-tile min of c
__device__ __align__(16) __nv_bfloat16 g_Ab[(size_t)B_ * D_];   // 4 MB
__device__ __align__(16) __nv_bfloat16 g_Bb[(size_t)N_ * D_];   // 4 MB
__device__ __align__(16) __nv_bfloat16 g_Dc[(size_t)B_ * N_];   // 32 MB: c = wsq - 2*dot

// ---------------------------------------------------------------------------
__device__ __forceinline__ uint32_t smem_to_u32(const void* p) {
    uint32_t a;
    asm("{ .reg .u64 t; cvta.to.shared.u64 t, %1; cvt.u32.u64 %0, t; }"
        : "=r"(a) : "l"(p));
    return a;
}

#define CP_ASYNC16(dst, src) \
    asm volatile("cp.async.cg.shared.global [%0], [%1], 16;" \
        :: "r"(dst), "l"(src) : "memory")
#define CP_COMMIT()  asm volatile("cp.async.commit_group;" ::: "memory")
#define CP_WAIT1()   asm volatile("cp.async.wait_group 1;"  ::: "memory")
#define CP_WAIT0()   asm volatile("cp.async.wait_group 0;"  ::: "memory")

#define LDSM4(r0, r1, r2, r3, addr) \
    asm volatile("ldmatrix.sync.aligned.m8n8.x4.shared.b16 {%0,%1,%2,%3}, [%4];" \
        : "=r"(r0), "=r"(r1), "=r"(r2), "=r"(r3) : "r"(addr))

#define MMA_BF16(d, a, b0v, b1v) \
    asm volatile("mma.sync.aligned.m16n8k16.row.col.f32.bf16.bf16.f32 " \
        "{%0,%1,%2,%3},{%4,%5,%6,%7},{%8,%9},{%0,%1,%2,%3};" \
        : "+f"((d)[0]), "+f"((d)[1]), "+f"((d)[2]), "+f"((d)[3]) \
        : "r"((a)[0]), "r"((a)[1]), "r"((a)[2]), "r"((a)[3]), \
          "r"(b0v), "r"(b1v))

// ---------------------------------------------------------------------------
// Kernel 1: fused row sum-of-squares + fp32->bf16 conversion.
// ---------------------------------------------------------------------------
__global__ void prep_kernel(const float* __restrict__ X,
                            const float* __restrict__ Wt) {
    int warp = (blockIdx.x * blockDim.x + threadIdx.x) >> 5;
    int lane = threadIdx.x & 31;
    if (warp >= B_ + N_) return;
    const bool isW = warp >= B_;
    const int row = isW ? warp - B_ : warp;
    const float* src = isW ? Wt : X;
    __nv_bfloat16* dst = isW ? g_Bb : g_Ab;

    const float4* p = (const float4*)(src + (size_t)row * D_);
    ushort4* d4 = (ushort4*)(dst + (size_t)row * D_);
    float s = 0.f;
    #pragma unroll
    for (int i = 0; i < 4; i++) {
        int v4 = lane + i * 32;
        float4 v = p[v4];
        s = fmaf(v.x, v.x, s); s = fmaf(v.y, v.y, s);
        s = fmaf(v.z, v.z, s); s = fmaf(v.w, v.w, s);
        ushort4 h;
        h.x = __bfloat16_as_ushort(__float2bfloat16_rn(v.x));
        h.y = __bfloat16_as_ushort(__float2bfloat16_rn(v.y));
        h.z = __bfloat16_as_ushort(__float2bfloat16_rn(v.z));
        h.w = __bfloat16_as_ushort(__float2bfloat16_rn(v.w));
        d4[v4] = h;
    }
    #pragma unroll
    for (int o = 16; o; o >>= 1) s += __shfl_xor_sync(0xffffffffu, s, o);
    if (lane == 0) { if (isW) g_wsq[row] = s; else g_xsq[row] = s; }
}

// ---------------------------------------------------------------------------
// Kernel 2: COARSE bf16 GEMM (M=128, N=128, K=512), m16n8k16.
// Byte-identical to the R9 kernel that measured 71.9us total
// (direct float2 epilogue stores, per-tile fp32 min partials).
// ---------------------------------------------------------------------------
__device__ __forceinline__ void load_stage(uint32_t sA, uint32_t sB,
                                           int arow0, int brow0, int kc0,
                                           int tid) {
    #pragma unroll
    for (int it = 0; it < 4; it++) {
        int id = tid + it * 256;
        int m = id >> 3, ch = id & 7;
        int chs = ch ^ (m & 7);
        CP_ASYNC16(sA + m * 128 + chs * 16,
                   g_Ab + (size_t)(arow0 + m) * D_ + kc0 + ch * 8);
    }
    #pragma unroll
    for (int it = 0; it < 4; it++) {
        int id = tid + it * 256;
        int n = id >> 3, ch = id & 7;
        int chs = ch ^ (n & 7);
        CP_ASYNC16(sB + n * 128 + chs * 16,
                   g_Bb + (size_t)(brow0 + n) * D_ + kc0 + ch * 8);
    }
}

extern "C" __global__ void __launch_bounds__(256, 2)
dist_tc_kernel() {
    extern __shared__ char smem[];
    const uint32_t sb = smem_to_u32(smem);
    const int tid = threadIdx.x;
    const int wid = tid >> 5;
    const int l   = tid & 31;
    const int rowBlk = blockIdx.y;
    const int colBlk = blockIdx.x;

    const int wm = (wid >> 2) * 64;
    const int wn = (wid & 3) * 32;
    const int arow0 = rowBlk * TM_;
    const int brow0 = colBlk * TN_;

    const int mrow = (l & 7) + ((l >> 3) & 1) * 8;
    const int aAdd = l >> 4;
    const int nrow = (l & 7) + (l >> 4) * 8;
    const int bAdd = (l >> 3) & 1;

    uint32_t aRowOff[4]; int aXr[4];
    #pragma unroll
    for (int i = 0; i < 4; i++) {
        int r = wm + i * 16 + mrow;
        aRowOff[i] = r * 128; aXr[i] = r & 7;
    }
    uint32_t bRowOff[2]; int bXr[2];
    #pragma unroll
    for (int jj = 0; jj < 2; jj++) {
        int r = wn + jj * 16 + nrow;
        bRowOff[jj] = r * 128; bXr[jj] = r & 7;
    }

    float acc[4][4][4];
    #pragma unroll
    for (int i = 0; i < 4; i++)
        #pragma unroll
        for (int j = 0; j < 4; j++)
            #pragma unroll
            for (int q = 0; q < 4; q++) acc[i][j][q] = 0.f;

    load_stage(sb, sb + 16384, arow0, brow0, 0, tid);
    CP_COMMIT();
    load_stage(sb + STAGE_BYTES, sb + STAGE_BYTES + 16384,
               arow0, brow0, KCH, tid);
    CP_COMMIT();

    for (int c = 0; c < NCH; c++) {
        CP_WAIT1();
        __syncthreads();

        if (c + 2 < NCH) {
            uint32_t st = sb + ((c + 2) % NSTAGE) * STAGE_BYTES;
            load_stage(st, st + 16384, arow0, brow0, (c + 2) * KCH, tid);
        }
        CP_COMMIT();

        const uint32_t Ab = sb + (c % NSTAGE) * STAGE_BYTES;
        const uint32_t Bb = Ab + 16384;

        #pragma unroll
        for (int ks = 0; ks < 4; ks++) {
            uint32_t ar[4][4];
            #pragma unroll
            for (int i = 0; i < 4; i++)
                LDSM4(ar[i][0], ar[i][1], ar[i][2], ar[i][3],
                      Ab + aRowOff[i] + (uint32_t)(((ks * 2 + aAdd) ^ aXr[i]) * 16));
            uint32_t br[4][2];
            #pragma unroll
            for (int jj = 0; jj < 2; jj++) {
                uint32_t r0, r1, r2, r3;
                LDSM4(r0, r1, r2, r3,
                      Bb + bRowOff[jj] + (uint32_t)(((ks * 2 + bAdd) ^ bXr[jj]) * 16));
                br[jj * 2][0] = r0;      br[jj * 2][1] = r1;
                br[jj * 2 + 1][0] = r2;  br[jj * 2 + 1][1] = r3;
            }
            #pragma unroll
            for (int i = 0; i < 4; i++)
                #pragma unroll
                for (int j = 0; j < 4; j++)
                    MMA_BF16(acc[i][j], ar[i], br[j][0], br[j][1]);
        }
    }
    CP_WAIT0();
    __syncthreads();

    // ---- epilogue: c = wsq - 2*dot -> bf16 g_Dc + per-tile fp32 min ----
    const int cbase = colBlk * TN_ + wn;
    float ws[4][2];
    #pragma unroll
    for (int j = 0; j < 4; j++) {
        ws[j][0] = g_wsq[cbase + j * 8 + (l & 3) * 2];
        ws[j][1] = g_wsq[cbase + j * 8 + (l & 3) * 2 + 1];
    }

    float* sVal = (float*)smem;            // [128][4]

    #pragma unroll
    for (int i = 0; i < 4; i++) {
        #pragma unroll
        for (int h = 0; h < 2; h++) {
            int lrow = wm + i * 16 + h * 8 + (l >> 2);
            int grow = arow0 + lrow;
            float bv = CUDART_INF_F;
            #pragma unroll
            for (int j = 0; j < 4; j++) {
                float cx = ws[j][0] - 2.0f * acc[i][j][h * 2 + 0];
                float cy = ws[j][1] - 2.0f * acc[i][j][h * 2 + 1];
                bv = fminf(bv, fminf(cx, cy));
                __nv_bfloat162 hh;
                hh.x = __float2bfloat16_rn(cx);
                hh.y = __float2bfloat16_rn(cy);
                *(__nv_bfloat162*)&g_Dc[(size_t)grow * N_ + cbase + j * 8 + (l & 3) * 2] = hh;
            }
            #pragma unroll
            for (int o = 1; o <= 2; o <<= 1)
                bv = fminf(bv, __shfl_xor_sync(0xffffffffu, bv, o));
            if ((l & 3) == 0) sVal[lrow * 4 + (wid & 3)] = bv;
        }
    }
    __syncthreads();

    if (tid < TM_) {
        float bv = fminf(fminf(sVal[tid * 4], sVal[tid * 4 + 1]),
                         fminf(sVal[tid * 4 + 2], sVal[tid * 4 + 3]));
        g_pval[colBlk * B_ + arow0 + tid] = bv;
    }
}

// ---------------------------------------------------------------------------
// Kernel 3: warp-per-row refine (R10 version — the single change vs R9).
// Coarse min over partials, uint4 scan of the bf16 c-row, exact fp32
// recompute of candidates with shfl-only reductions. No __syncthreads.
// ---------------------------------------------------------------------------
__global__ void __launch_bounds__(256)
refine_kernel(const float* __restrict__ X, const float* __restrict__ Wt,
              float* __restrict__ out) {
    const int w    = threadIdx.x >> 5;
    const int lane = threadIdx.x & 31;
    const int row  = blockIdx.x * RW + w;

    __shared__ int s_cand[RW][MAXCAND];
    __shared__ int s_cnt[RW];

    // 1) coarse row min of c from the 32 tile partials
    float m = g_pval[lane * B_ + row];
    #pragma unroll
    for (int o = 16; o; o >>= 1)
        m = fminf(m, __shfl_xor_sync(0xffffffffu, m, o));
    const float thresh = m + BAND;
    if (lane == 0) s_cnt[w] = 0;
    __syncwarp();

    // 2) candidate scan (8 bf16 per uint4 load)
    const uint4* p4 = (const uint4*)(g_Dc + (size_t)row * N_);
    #pragma unroll 4
    for (int it = 0; it < 16; it++) {
        uint4 v = p4[lane + it * 32];
        uint32_t wv[4] = {v.x, v.y, v.z, v.w};
        int colbase = (lane + it * 32) * 8;
        #pragma unroll
        for (int k = 0; k < 4; k++) {
            __nv_bfloat162 hv = *(__nv_bfloat162*)&wv[k];
            float c0 = __bfloat162float(hv.x);
            float c1 = __bfloat162float(hv.y);
            if (c0 < thresh) {
                int p = atomicAdd(&s_cnt[w], 1);
                if (p < MAXCAND) s_cand[w][p] = colbase + k * 2;
            }
            if (c1 < thresh) {
                int p = atomicAdd(&s_cnt[w], 1);
                if (p < MAXCAND) s_cand[w][p] = colbase + k * 2 + 1;
            }
        }
    }
    __syncwarp();
    const int cnt = min(s_cnt[w], MAXCAND);

    // 3) exact fp32 evaluation of candidates
    float xr[16];
    #pragma unroll
    for (int i = 0; i < 16; i++) xr[i] = X[(size_t)row * D_ + lane + i * 32];
    const float xs = g_xsq[row];

    float bestV = CUDART_INF_F;
    int   bestI = 0x7fffffff;
    for (int c = 0; c < cnt; c++) {
        int col = s_cand[w][c];
        const float* wr = Wt + (size_t)col * D_;
        float part = 0.f;
        #pragma unroll
        for (int i = 0; i < 16; i++)
            part = fmaf(xr[i], wr[lane + i * 32], part);
        #pragma unroll
        for (int o = 16; o; o >>= 1)
            part += __shfl_xor_sync(0xffffffffu, part, o);
        float v = fmaxf((xs - 2.0f * part) + g_wsq[col], 0.0f);
        if (v < bestV || (v == bestV && col < bestI)) { bestV = v; bestI = col; }
    }

    if (lane == 0) {
        out[row * 2 + 0]  = (float)(bestI >> 6);
        out[row * 2 + 1]  = (float)(bestI & (GW - 1));
        out[2 * B_ + row] = sqrtf(bestV);
    }
}

// ---------------------------------------------------------------------------
extern "C" void kernel_launch(void* const* d_in, const int* in_sizes, int n_in,
                              void* d_out, int out_size) {
    const float* X  = (const float*)d_in[0];
    const float* Wt = (const float*)d_in[1];
    float* out = (float*)d_out;

    cudaFuncSetAttribute(dist_tc_kernel,
                         cudaFuncAttributeMaxDynamicSharedMemorySize, SM_TOTAL);

    // 1) fused sqsum + bf16 conversion
    prep_kernel<<<(B_ + N_) / 8, 256>>>(X, Wt);

    // 2) coarse bf16 distance GEMM (K=512, m16n8k16) — R9-identical
    dim3 grid(N_ / TN_, B_ / TM_);   // (32, 32)
    dist_tc_kernel<<<grid, 256, SM_TOTAL>>>();

    // 3) warp-per-row candidate refine + outputs
    refine_kernel<<<B_ / RW, 256>>>(X, Wt, out);
}

// round 13
// speedup vs baseline: 1.0917x; 1.0297x over previous
#include <cuda_runtime.h>
#include <cuda_bf16.h>
#include <math_constants.h>
#include <cstdint>

// Problem constants
#define B_      4096
#define N_      4096
#define D_      512
#define GW      64
#define KCH     64            // bf16 K per chunk (128B rows)
#define NCH     (D_/KCH)      // 8 chunks
#define TM_     128
#define TN_     128
#define NCOLBLK (N_/TN_)      // 32
#define NSTAGE  3
#define STAGE_BYTES 32768     // A 16KB + B 16KB
#define SM_TOTAL (NSTAGE*STAGE_BYTES)   // 96 KB -> 2 CTAs/SM
#define BAND    0.35f
#define MAXCAND 128
#define RW      8             // refine warps (rows) per block
#define NTH     128           // GEMM threads (4 warps, 2x2 of 64x64)

// Scratch globals
__device__ float g_xsq[B_];
__device__ float g_wsq[N_];
__device__ float g_pval[NCOLBLK * B_];                     // per-tile min of c
__device__ __align__(16) __nv_bfloat16 g_Ab[(size_t)B_ * D_];   // 4 MB
__device__ __align__(16) __nv_bfloat16 g_Bb[(size_t)N_ * D_];   // 4 MB
__device__ __align__(16) __nv_bfloat16 g_Dc[(size_t)B_ * N_];   // 32 MB: c = wsq - 2*dot

// ---------------------------------------------------------------------------
__device__ __forceinline__ uint32_t smem_to_u32(const void* p) {
    uint32_t a;
    asm("{ .reg .u64 t; cvta.to.shared.u64 t, %1; cvt.u32.u64 %0, t; }"
        : "=r"(a) : "l"(p));
    return a;
}

#define CP_ASYNC16(dst, src) \
    asm volatile("cp.async.cg.shared.global [%0], [%1], 16;" \
        :: "r"(dst), "l"(src) : "memory")
#define CP_COMMIT()  asm volatile("cp.async.commit_group;" ::: "memory")
#define CP_WAIT1()   asm volatile("cp.async.wait_group 1;"  ::: "memory")
#define CP_WAIT0()   asm volatile("cp.async.wait_group 0;"  ::: "memory")

#define LDSM4(r0, r1, r2, r3, addr) \
    asm volatile("ldmatrix.sync.aligned.m8n8.x4.shared.b16 {%0,%1,%2,%3}, [%4];" \
        : "=r"(r0), "=r"(r1), "=r"(r2), "=r"(r3) : "r"(addr))

#define MMA_BF16(d, a, b0v, b1v) \
    asm volatile("mma.sync.aligned.m16n8k16.row.col.f32.bf16.bf16.f32 " \
        "{%0,%1,%2,%3},{%4,%5,%6,%7},{%8,%9},{%0,%1,%2,%3};" \
        : "+f"((d)[0]), "+f"((d)[1]), "+f"((d)[2]), "+f"((d)[3]) \
        : "r"((a)[0]), "r"((a)[1]), "r"((a)[2]), "r"((a)[3]), \
          "r"(b0v), "r"(b1v))

// ---------------------------------------------------------------------------
// Kernel 1: fused row sum-of-squares + fp32->bf16 conversion. (unchanged)
// ---------------------------------------------------------------------------
__global__ void prep_kernel(const float* __restrict__ X,
                            const float* __restrict__ Wt) {
    int warp = (blockIdx.x * blockDim.x + threadIdx.x) >> 5;
    int lane = threadIdx.x & 31;
    if (warp >= B_ + N_) return;
    const bool isW = warp >= B_;
    const int row = isW ? warp - B_ : warp;
    const float* src = isW ? Wt : X;
    __nv_bfloat16* dst = isW ? g_Bb : g_Ab;

    const float4* p = (const float4*)(src + (size_t)row * D_);
    ushort4* d4 = (ushort4*)(dst + (size_t)row * D_);
    float s = 0.f;
    #pragma unroll
    for (int i = 0; i < 4; i++) {
        int v4 = lane + i * 32;
        float4 v = p[v4];
        s = fmaf(v.x, v.x, s); s = fmaf(v.y, v.y, s);
        s = fmaf(v.z, v.z, s); s = fmaf(v.w, v.w, s);
        ushort4 h;
        h.x = __bfloat16_as_ushort(__float2bfloat16_rn(v.x));
        h.y = __bfloat16_as_ushort(__float2bfloat16_rn(v.y));
        h.z = __bfloat16_as_ushort(__float2bfloat16_rn(v.z));
        h.w = __bfloat16_as_ushort(__float2bfloat16_rn(v.w));
        d4[v4] = h;
    }
    #pragma unroll
    for (int o = 16; o; o >>= 1) s += __shfl_xor_sync(0xffffffffu, s, o);
    if (lane == 0) { if (isW) g_wsq[row] = s; else g_xsq[row] = s; }
}

// ---------------------------------------------------------------------------
// Kernel 2: COARSE bf16 GEMM (M=128, N=128, K=512), m16n8k16.
// CHANGED: 4 warps (2x2), 64x64 warp tiles -> 64KB LDS per chunk (was 96KB).
// Warp-internal lane maps, swizzle, pipeline structure unchanged.
// ---------------------------------------------------------------------------
__device__ __forceinline__ void load_stage(uint32_t sA, uint32_t sB,
                                           int arow0, int brow0, int kc0,
                                           int tid) {
    #pragma unroll
    for (int it = 0; it < 8; it++) {
        int id = tid + it * NTH;
        int m = id >> 3, ch = id & 7;
        int chs = ch ^ (m & 7);
        CP_ASYNC16(sA + m * 128 + chs * 16,
                   g_Ab + (size_t)(arow0 + m) * D_ + kc0 + ch * 8);
    }
    #pragma unroll
    for (int it = 0; it < 8; it++) {
        int id = tid + it * NTH;
        int n = id >> 3, ch = id & 7;
        int chs = ch ^ (n & 7);
        CP_ASYNC16(sB + n * 128 + chs * 16,
                   g_Bb + (size_t)(brow0 + n) * D_ + kc0 + ch * 8);
    }
}

extern "C" __global__ void __launch_bounds__(NTH, 2)
dist_tc_kernel() {
    extern __shared__ char smem[];
    const uint32_t sb = smem_to_u32(smem);
    const int tid = threadIdx.x;
    const int wid = tid >> 5;
    const int l   = tid & 31;
    const int rowBlk = blockIdx.y;
    const int colBlk = blockIdx.x;

    const int wm = (wid >> 1) * 64;     // 2 m-groups
    const int wn = (wid & 1) * 64;      // 2 n-groups
    const int arow0 = rowBlk * TM_;
    const int brow0 = colBlk * TN_;

    const int mrow = (l & 7) + ((l >> 3) & 1) * 8;
    const int aAdd = l >> 4;
    const int nrow = (l & 7) + (l >> 4) * 8;
    const int bAdd = (l >> 3) & 1;

    uint32_t aRowOff[4]; int aXr[4];
    #pragma unroll
    for (int i = 0; i < 4; i++) {
        int r = wm + i * 16 + mrow;
        aRowOff[i] = r * 128; aXr[i] = r & 7;
    }
    uint32_t bRowOff[4]; int bXr[4];
    #pragma unroll
    for (int jj = 0; jj < 4; jj++) {
        int r = wn + jj * 16 + nrow;
        bRowOff[jj] = r * 128; bXr[jj] = r & 7;
    }

    float acc[4][8][4];
    #pragma unroll
    for (int i = 0; i < 4; i++)
        #pragma unroll
        for (int j = 0; j < 8; j++)
            #pragma unroll
            for (int q = 0; q < 4; q++) acc[i][j][q] = 0.f;

    load_stage(sb, sb + 16384, arow0, brow0, 0, tid);
    CP_COMMIT();
    load_stage(sb + STAGE_BYTES, sb + STAGE_BYTES + 16384,
               arow0, brow0, KCH, tid);
    CP_COMMIT();

    for (int c = 0; c < NCH; c++) {
        CP_WAIT1();
        __syncthreads();

        if (c + 2 < NCH) {
            uint32_t st = sb + ((c + 2) % NSTAGE) * STAGE_BYTES;
            load_stage(st, st + 16384, arow0, brow0, (c + 2) * KCH, tid);
        }
        CP_COMMIT();

        const uint32_t Ab = sb + (c % NSTAGE) * STAGE_BYTES;
        const uint32_t Bb = Ab + 16384;

        #pragma unroll
        for (int ks = 0; ks < 4; ks++) {
            uint32_t ar[4][4];
            #pragma unroll
            for (int i = 0; i < 4; i++)
                LDSM4(ar[i][0], ar[i][1], ar[i][2], ar[i][3],
                      Ab + aRowOff[i] + (uint32_t)(((ks * 2 + aAdd) ^ aXr[i]) * 16));
            uint32_t br[8][2];
            #pragma unroll
            for (int jj = 0; jj < 4; jj++) {
                uint32_t r0, r1, r2, r3;
                LDSM4(r0, r1, r2, r3,
                      Bb + bRowOff[jj] + (uint32_t)(((ks * 2 + bAdd) ^ bXr[jj]) * 16));
                br[jj * 2][0] = r0;      br[jj * 2][1] = r1;
                br[jj * 2 + 1][0] = r2;  br[jj * 2 + 1][1] = r3;
            }
            #pragma unroll
            for (int i = 0; i < 4; i++)
                #pragma unroll
                for (int j = 0; j < 8; j++)
                    MMA_BF16(acc[i][j], ar[i], br[j][0], br[j][1]);
        }
    }
    CP_WAIT0();
    __syncthreads();

    // ---- epilogue: c = wsq - 2*dot -> bf16 g_Dc + per-tile fp32 min ----
    const int cbase = colBlk * TN_ + wn;
    float ws[8][2];
    #pragma unroll
    for (int j = 0; j < 8; j++) {
        ws[j][0] = g_wsq[cbase + j * 8 + (l & 3) * 2];
        ws[j][1] = g_wsq[cbase + j * 8 + (l & 3) * 2 + 1];
    }

    float* sVal = (float*)smem;            // [128][2]

    #pragma unroll
    for (int i = 0; i < 4; i++) {
        #pragma unroll
        for (int h = 0; h < 2; h++) {
            int lrow = wm + i * 16 + h * 8 + (l >> 2);
            int grow = arow0 + lrow;
            float bv = CUDART_INF_F;
            #pragma unroll
            for (int j = 0; j < 8; j++) {
                float cx = ws[j][0] - 2.0f * acc[i][j][h * 2 + 0];
                float cy = ws[j][1] - 2.0f * acc[i][j][h * 2 + 1];
                bv = fminf(bv, fminf(cx, cy));
                __nv_bfloat162 hh;
                hh.x = __float2bfloat16_rn(cx);
                hh.y = __float2bfloat16_rn(cy);
                *(__nv_bfloat162*)&g_Dc[(size_t)grow * N_ + cbase + j * 8 + (l & 3) * 2] = hh;
            }
            #pragma unroll
            for (int o = 1; o <= 2; o <<= 1)
                bv = fminf(bv, __shfl_xor_sync(0xffffffffu, bv, o));
            if ((l & 3) == 0) sVal[lrow * 2 + (wid & 1)] = bv;
        }
    }
    __syncthreads();

    {   // all 128 threads: merge the 2 n-warp partials per row
        float bv = fminf(sVal[tid * 2], sVal[tid * 2 + 1]);
        g_pval[colBlk * B_ + arow0 + tid] = bv;
    }
}

// ---------------------------------------------------------------------------
// Kernel 3: warp-per-row refine. (unchanged from R11)
// ---------------------------------------------------------------------------
__global__ void __launch_bounds__(256)
refine_kernel(const float* __restrict__ X, const float* __restrict__ Wt,
              float* __restrict__ out) {
    const int w    = threadIdx.x >> 5;
    const int lane = threadIdx.x & 31;
    const int row  = blockIdx.x * RW + w;

    __shared__ int s_cand[RW][MAXCAND];
    __shared__ int s_cnt[RW];

    float m = g_pval[lane * B_ + row];
    #pragma unroll
    for (int o = 16; o; o >>= 1)
        m = fminf(m, __shfl_xor_sync(0xffffffffu, m, o));
    const float thresh = m + BAND;
    if (lane == 0) s_cnt[w] = 0;
    __syncwarp();

    const uint4* p4 = (const uint4*)(g_Dc + (size_t)row * N_);
    #pragma unroll 4
    for (int it = 0; it < 16; it++) {
        uint4 v = p4[lane + it * 32];
        uint32_t wv[4] = {v.x, v.y, v.z, v.w};
        int colbase = (lane + it * 32) * 8;
        #pragma unroll
        for (int k = 0; k < 4; k++) {
            __nv_bfloat162 hv = *(__nv_bfloat162*)&wv[k];
            float c0 = __bfloat162float(hv.x);
            float c1 = __bfloat162float(hv.y);
            if (c0 < thresh) {
                int p = atomicAdd(&s_cnt[w], 1);
                if (p < MAXCAND) s_cand[w][p] = colbase + k * 2;
            }
            if (c1 < thresh) {
                int p = atomicAdd(&s_cnt[w], 1);
                if (p < MAXCAND) s_cand[w][p] = colbase + k * 2 + 1;
            }
        }
    }
    __syncwarp();
    const int cnt = min(s_cnt[w], MAXCAND);

    float xr[16];
    #pragma unroll
    for (int i = 0; i < 16; i++) xr[i] = X[(size_t)row * D_ + lane + i * 32];
    const float xs = g_xsq[row];

    float bestV = CUDART_INF_F;
    int   bestI = 0x7fffffff;
    for (int c = 0; c < cnt; c++) {
        int col = s_cand[w][c];
        const float* wr = Wt + (size_t)col * D_;
        float part = 0.f;
        #pragma unroll
        for (int i = 0; i < 16; i++)
            part = fmaf(xr[i], wr[lane + i * 32], part);
        #pragma unroll
        for (int o = 16; o; o >>= 1)
            part += __shfl_xor_sync(0xffffffffu, part, o);
        float v = fmaxf((xs - 2.0f * part) + g_wsq[col], 0.0f);
        if (v < bestV || (v == bestV && col < bestI)) { bestV = v; bestI = col; }
    }

    if (lane == 0) {
        out[row * 2 + 0]  = (float)(bestI >> 6);
        out[row * 2 + 1]  = (float)(bestI & (GW - 1));
        out[2 * B_ + row] = sqrtf(bestV);
    }
}

// ---------------------------------------------------------------------------
extern "C" void kernel_launch(void* const* d_in, const int* in_sizes, int n_in,
                              void* d_out, int out_size) {
    const float* X  = (const float*)d_in[0];
    const float* Wt = (const float*)d_in[1];
    float* out = (float*)d_out;

    cudaFuncSetAttribute(dist_tc_kernel,
                         cudaFuncAttributeMaxDynamicSharedMemorySize, SM_TOTAL);

    // 1) fused sqsum + bf16 conversion
    prep_kernel<<<(B_ + N_) / 8, 256>>>(X, Wt);

    // 2) coarse bf16 distance GEMM — 4 warps, 64x64 warp tiles
    dim3 grid(N_ / TN_, B_ / TM_);   // (32, 32)
    dist_tc_kernel<<<grid, NTH, SM_TOTAL>>>();

    // 3) warp-per-row candidate refine + outputs
    refine_kernel<<<B_ / RW, 256>>>(X, Wt, out);
}

// round 14
// speedup vs baseline: 1.1023x; 1.0097x over previous
#include <cuda_runtime.h>
#include <cuda_bf16.h>
#include <math_constants.h>
#include <cstdint>

// Problem constants
#define B_      4096
#define N_      4096
#define D_      512
#define GW      64
#define KCH     64            // bf16 K per chunk (128B rows)
#define NCHT    8             // chunks per tile (D_/KCH)
#define TM_     128
#define TN_     128
#define NTILES  1024          // (B_/TM_)*(N_/TN_)
#define NCOLBLK (N_/TN_)      // 32
#define NPERS   296           // persistent CTAs = 148 SMs * 2
#define NSTAGE  3
#define STAGE_BYTES 32768     // A 16KB + B 16KB
#define SVAL_OFF (NSTAGE*STAGE_BYTES)          // 98304
#define SM_TOTAL (SVAL_OFF + 1024)             // +1KB dedicated sVal
#define BAND    0.35f
#define MAXCAND 128
#define RW      8             // refine warps (rows) per block
#define NTH     128           // GEMM threads (4 warps, 2x2 of 64x64)

// Scratch globals
__device__ float g_xsq[B_];
__device__ float g_wsq[N_];
__device__ float g_pval[NCOLBLK * B_];                     // per-tile min of c
__device__ __align__(16) __nv_bfloat16 g_Ab[(size_t)B_ * D_];   // 4 MB
__device__ __align__(16) __nv_bfloat16 g_Bb[(size_t)N_ * D_];   // 4 MB
__device__ __align__(16) __nv_bfloat16 g_Dc[(size_t)B_ * N_];   // 32 MB: c = wsq - 2*dot

// ---------------------------------------------------------------------------
__device__ __forceinline__ uint32_t smem_to_u32(const void* p) {
    uint32_t a;
    asm("{ .reg .u64 t; cvta.to.shared.u64 t, %1; cvt.u32.u64 %0, t; }"
        : "=r"(a) : "l"(p));
    return a;
}

#define CP_ASYNC16(dst, src) \
    asm volatile("cp.async.cg.shared.global [%0], [%1], 16;" \
        :: "r"(dst), "l"(src) : "memory")
#define CP_COMMIT()  asm volatile("cp.async.commit_group;" ::: "memory")
#define CP_WAIT1()   asm volatile("cp.async.wait_group 1;"  ::: "memory")
#define CP_WAIT0()   asm volatile("cp.async.wait_group 0;"  ::: "memory")

#define LDSM4(r0, r1, r2, r3, addr) \
    asm volatile("ldmatrix.sync.aligned.m8n8.x4.shared.b16 {%0,%1,%2,%3}, [%4];" \
        : "=r"(r0), "=r"(r1), "=r"(r2), "=r"(r3) : "r"(addr))

#define MMA_BF16(d, a, b0v, b1v) \
    asm volatile("mma.sync.aligned.m16n8k16.row.col.f32.bf16.bf16.f32 " \
        "{%0,%1,%2,%3},{%4,%5,%6,%7},{%8,%9},{%0,%1,%2,%3};" \
        : "+f"((d)[0]), "+f"((d)[1]), "+f"((d)[2]), "+f"((d)[3]) \
        : "r"((a)[0]), "r"((a)[1]), "r"((a)[2]), "r"((a)[3]), \
          "r"(b0v), "r"(b1v))

// ---------------------------------------------------------------------------
// Kernel 1: fused row sum-of-squares + fp32->bf16 conversion. (unchanged)
// ---------------------------------------------------------------------------
__global__ void prep_kernel(const float* __restrict__ X,
                            const float* __restrict__ Wt) {
    int warp = (blockIdx.x * blockDim.x + threadIdx.x) >> 5;
    int lane = threadIdx.x & 31;
    if (warp >= B_ + N_) return;
    const bool isW = warp >= B_;
    const int row = isW ? warp - B_ : warp;
    const float* src = isW ? Wt : X;
    __nv_bfloat16* dst = isW ? g_Bb : g_Ab;

    const float4* p = (const float4*)(src + (size_t)row * D_);
    ushort4* d4 = (ushort4*)(dst + (size_t)row * D_);
    float s = 0.f;
    #pragma unroll
    for (int i = 0; i < 4; i++) {
        int v4 = lane + i * 32;
        float4 v = p[v4];
        s = fmaf(v.x, v.x, s); s = fmaf(v.y, v.y, s);
        s = fmaf(v.z, v.z, s); s = fmaf(v.w, v.w, s);
        ushort4 h;
        h.x = __bfloat16_as_ushort(__float2bfloat16_rn(v.x));
        h.y = __bfloat16_as_ushort(__float2bfloat16_rn(v.y));
        h.z = __bfloat16_as_ushort(__float2bfloat16_rn(v.z));
        h.w = __bfloat16_as_ushort(__float2bfloat16_rn(v.w));
        d4[v4] = h;
    }
    #pragma unroll
    for (int o = 16; o; o >>= 1) s += __shfl_xor_sync(0xffffffffu, s, o);
    if (lane == 0) { if (isW) g_wsq[row] = s; else g_xsq[row] = s; }
}

// ---------------------------------------------------------------------------
// Stage loader (unchanged body; addressed by tile coords + k offset)
// ---------------------------------------------------------------------------
__device__ __forceinline__ void load_stage(uint32_t sA, uint32_t sB,
                                           int arow0, int brow0, int kc0,
                                           int tid) {
    #pragma unroll
    for (int it = 0; it < 8; it++) {
        int id = tid + it * NTH;
        int m = id >> 3, ch = id & 7;
        int chs = ch ^ (m & 7);
        CP_ASYNC16(sA + m * 128 + chs * 16,
                   g_Ab + (size_t)(arow0 + m) * D_ + kc0 + ch * 8);
    }
    #pragma unroll
    for (int it = 0; it < 8; it++) {
        int id = tid + it * NTH;
        int n = id >> 3, ch = id & 7;
        int chs = ch ^ (n & 7);
        CP_ASYNC16(sB + n * 128 + chs * 16,
                   g_Bb + (size_t)(brow0 + n) * D_ + kc0 + ch * 8);
    }
}

// ---------------------------------------------------------------------------
// Kernel 2: PERSISTENT coarse bf16 GEMM. 296 CTAs; each owns tiles
// bid, bid+296, ... and runs one flat chunk loop over all of them, so the
// cp.async pipeline stays warm across tile boundaries and each epilogue
// overlaps the next tile's loads. Inner chunk body identical to R12.
// ---------------------------------------------------------------------------
extern "C" __global__ void __launch_bounds__(NTH, 2)
dist_tc_kernel() {
    extern __shared__ char smem[];
    const uint32_t sb = smem_to_u32(smem);
    const int tid = threadIdx.x;
    const int wid = tid >> 5;
    const int l   = tid & 31;

    // tile list for this persistent CTA
    int myTiles[4]; int nt = 0;
    for (int t = blockIdx.x; t < NTILES; t += NPERS) myTiles[nt++] = t;
    const int totFC = nt * NCHT;

    const int wm = (wid >> 1) * 64;
    const int wn = (wid & 1) * 64;

    // warp-internal lane geometry (tile-invariant)
    const int mrow = (l & 7) + ((l >> 3) & 1) * 8;
    const int aAdd = l >> 4;
    const int nrow = (l & 7) + (l >> 4) * 8;
    const int bAdd = (l >> 3) & 1;

    uint32_t aRowOff[4]; int aXr[4];
    #pragma unroll
    for (int i = 0; i < 4; i++) {
        int r = wm + i * 16 + mrow;
        aRowOff[i] = r * 128; aXr[i] = r & 7;
    }
    uint32_t bRowOff[4]; int bXr[4];
    #pragma unroll
    for (int jj = 0; jj < 4; jj++) {
        int r = wn + jj * 16 + nrow;
        bRowOff[jj] = r * 128; bXr[jj] = r & 7;
    }

    float acc[4][8][4];
    #pragma unroll
    for (int i = 0; i < 4; i++)
        #pragma unroll
        for (int j = 0; j < 8; j++)
            #pragma unroll
            for (int q = 0; q < 4; q++) acc[i][j][q] = 0.f;

    float* sVal = (float*)(smem + SVAL_OFF);   // [128][2], outside stages

    // prologue: flat chunks 0, 1
    {
        int t0 = myTiles[0];
        load_stage(sb, sb + 16384, (t0 >> 5) * TM_, (t0 & 31) * TN_, 0, tid);
        CP_COMMIT();
        load_stage(sb + STAGE_BYTES, sb + STAGE_BYTES + 16384,
                   (t0 >> 5) * TM_, (t0 & 31) * TN_, KCH, tid);
        CP_COMMIT();
    }

    for (int fc = 0; fc < totFC; fc++) {
        CP_WAIT1();
        __syncthreads();

        if (fc + 2 < totFC) {
            int nfc = fc + 2;
            int t = myTiles[nfc >> 3];
            uint32_t st = sb + (nfc % NSTAGE) * STAGE_BYTES;
            load_stage(st, st + 16384,
                       (t >> 5) * TM_, (t & 31) * TN_, (nfc & 7) * KCH, tid);
        }
        CP_COMMIT();

        const uint32_t Ab = sb + (fc % NSTAGE) * STAGE_BYTES;
        const uint32_t Bb = Ab + 16384;

        #pragma unroll
        for (int ks = 0; ks < 4; ks++) {
            uint32_t ar[4][4];
            #pragma unroll
            for (int i = 0; i < 4; i++)
                LDSM4(ar[i][0], ar[i][1], ar[i][2], ar[i][3],
                      Ab + aRowOff[i] + (uint32_t)(((ks * 2 + aAdd) ^ aXr[i]) * 16));
            uint32_t br[8][2];
            #pragma unroll
            for (int jj = 0; jj < 4; jj++) {
                uint32_t r0, r1, r2, r3;
                LDSM4(r0, r1, r2, r3,
                      Bb + bRowOff[jj] + (uint32_t)(((ks * 2 + bAdd) ^ bXr[jj]) * 16));
                br[jj * 2][0] = r0;      br[jj * 2][1] = r1;
                br[jj * 2 + 1][0] = r2;  br[jj * 2 + 1][1] = r3;
            }
            #pragma unroll
            for (int i = 0; i < 4; i++)
                #pragma unroll
                for (int j = 0; j < 8; j++)
                    MMA_BF16(acc[i][j], ar[i], br[j][0], br[j][1]);
        }

        // ---- tile boundary: epilogue (overlaps next tile's cp.async) ----
        if ((fc & 7) == 7) {
            int t = myTiles[fc >> 3];
            int arow0  = (t >> 5) * TM_;
            int colBlk = t & 31;
            const int cbase = colBlk * TN_ + wn;

            float ws[8][2];
            #pragma unroll
            for (int j = 0; j < 8; j++) {
                ws[j][0] = g_wsq[cbase + j * 8 + (l & 3) * 2];
                ws[j][1] = g_wsq[cbase + j * 8 + (l & 3) * 2 + 1];
            }

            #pragma unroll
            for (int i = 0; i < 4; i++) {
                #pragma unroll
                for (int h = 0; h < 2; h++) {
                    int lrow = wm + i * 16 + h * 8 + (l >> 2);
                    int grow = arow0 + lrow;
                    float bv = CUDART_INF_F;
                    #pragma unroll
                    for (int j = 0; j < 8; j++) {
                        float cx = ws[j][0] - 2.0f * acc[i][j][h * 2 + 0];
                        float cy = ws[j][1] - 2.0f * acc[i][j][h * 2 + 1];
                        bv = fminf(bv, fminf(cx, cy));
                        __nv_bfloat162 hh;
                        hh.x = __float2bfloat16_rn(cx);
                        hh.y = __float2bfloat16_rn(cy);
                        *(__nv_bfloat162*)&g_Dc[(size_t)grow * N_ + cbase + j * 8 + (l & 3) * 2] = hh;
                    }
                    #pragma unroll
                    for (int o = 1; o <= 2; o <<= 1)
                        bv = fminf(bv, __shfl_xor_sync(0xffffffffu, bv, o));
                    if ((l & 3) == 0) sVal[lrow * 2 + (wid & 1)] = bv;
                }
            }
            __syncthreads();
            g_pval[colBlk * B_ + arow0 + tid] =
                fminf(sVal[tid * 2], sVal[tid * 2 + 1]);

            // reset accumulators for the next tile
            #pragma unroll
            for (int i = 0; i < 4; i++)
                #pragma unroll
                for (int j = 0; j < 8; j++)
                    #pragma unroll
                    for (int q = 0; q < 4; q++) acc[i][j][q] = 0.f;
        }
    }
}

// ---------------------------------------------------------------------------
// Kernel 3: warp-per-row refine. (unchanged)
// ---------------------------------------------------------------------------
__global__ void __launch_bounds__(256)
refine_kernel(const float* __restrict__ X, const float* __restrict__ Wt,
              float* __restrict__ out) {
    const int w    = threadIdx.x >> 5;
    const int lane = threadIdx.x & 31;
    const int row  = blockIdx.x * RW + w;

    __shared__ int s_cand[RW][MAXCAND];
    __shared__ int s_cnt[RW];

    float m = g_pval[lane * B_ + row];
    #pragma unroll
    for (int o = 16; o; o >>= 1)
        m = fminf(m, __shfl_xor_sync(0xffffffffu, m, o));
    const float thresh = m + BAND;
    if (lane == 0) s_cnt[w] = 0;
    __syncwarp();

    const uint4* p4 = (const uint4*)(g_Dc + (size_t)row * N_);
    #pragma unroll 4
    for (int it = 0; it < 16; it++) {
        uint4 v = p4[lane + it * 32];
        uint32_t wv[4] = {v.x, v.y, v.z, v.w};
        int colbase = (lane + it * 32) * 8;
        #pragma unroll
        for (int k = 0; k < 4; k++) {
            __nv_bfloat162 hv = *(__nv_bfloat162*)&wv[k];
            float c0 = __bfloat162float(hv.x);
            float c1 = __bfloat162float(hv.y);
            if (c0 < thresh) {
                int p = atomicAdd(&s_cnt[w], 1);
                if (p < MAXCAND) s_cand[w][p] = colbase + k * 2;
            }
            if (c1 < thresh) {
                int p = atomicAdd(&s_cnt[w], 1);
                if (p < MAXCAND) s_cand[w][p] = colbase + k * 2 + 1;
            }
        }
    }
    __syncwarp();
    const int cnt = min(s_cnt[w], MAXCAND);

    float xr[16];
    #pragma unroll
    for (int i = 0; i < 16; i++) xr[i] = X[(size_t)row * D_ + lane + i * 32];
    const float xs = g_xsq[row];

    float bestV = CUDART_INF_F;
    int   bestI = 0x7fffffff;
    for (int c = 0; c < cnt; c++) {
        int col = s_cand[w][c];
        const float* wr = Wt + (size_t)col * D_;
        float part = 0.f;
        #pragma unroll
        for (int i = 0; i < 16; i++)
            part = fmaf(xr[i], wr[lane + i * 32], part);
        #pragma unroll
        for (int o = 16; o; o >>= 1)
            part += __shfl_xor_sync(0xffffffffu, part, o);
        float v = fmaxf((xs - 2.0f * part) + g_wsq[col], 0.0f);
        if (v < bestV || (v == bestV && col < bestI)) { bestV = v; bestI = col; }
    }

    if (lane == 0) {
        out[row * 2 + 0]  = (float)(bestI >> 6);
        out[row * 2 + 1]  = (float)(bestI & (GW - 1));
        out[2 * B_ + row] = sqrtf(bestV);
    }
}

// ---------------------------------------------------------------------------
extern "C" void kernel_launch(void* const* d_in, const int* in_sizes, int n_in,
                              void* d_out, int out_size) {
    const float* X  = (const float*)d_in[0];
    const float* Wt = (const float*)d_in[1];
    float* out = (float*)d_out;

    cudaFuncSetAttribute(dist_tc_kernel,
                         cudaFuncAttributeMaxDynamicSharedMemorySize, SM_TOTAL);

    // 1) fused sqsum + bf16 conversion
    prep_kernel<<<(B_ + N_) / 8, 256>>>(X, Wt);

    // 2) persistent coarse bf16 distance GEMM
    dist_tc_kernel<<<NPERS, NTH, SM_TOTAL>>>();

    // 3) warp-per-row candidate refine + outputs
    refine_kernel<<<B_ / RW, 256>>>(X, Wt, out);
}